// round 15
// baseline (speedup 1.0000x reference)
#include <cuda_runtime.h>
#include <cuda_fp16.h>
#include <cstdint>

// ---------------------------------------------------------------------------
// ConditionalRealNVP log_prob — R13: R12 (f16 hidden path) + dual-tile pairs.
// Each iteration processes TWO 128-row tiles at 16 warps / 512 threads:
// every B-weight fragment group feeds both tiles' MMAs, halving B-LDSM
// bytes per row (L1 was 64%). f16 accumulators (R12) free exactly the
// registers that made this layout spill in bf16 (R11): axp 40 + acc 32 +
// bf 16 + hfr 32..64 stays ~120 <= 128. One __syncthreads per iteration.
// ---------------------------------------------------------------------------

#define BTOT   524288
#define NPAIRS (BTOT / 256)     // 2048
#define XP_LD  88
#define W_LD   264
#define W3_LD  16
#define NTHREADS 512
#define XP_T   22528            // one tile's xp bytes (128*88*2)
#define XP_P   45056            // one buffer (pair of tiles)

// smem byte offsets
#define OFF_W1  0               // 80*264*2  = 42240
#define OFF_W2  42240           // 128*264*2 = 67584
#define OFF_W3  109824          // 128*16*2  = 4096
#define OFF_XP  113920          // 2 buf x 45056 = 90112
#define OFF_XA  204032          // 2 buf x 4096  = 8192
#define OFF_B1  212224          // 512 (128 half2)
#define OFF_B2  212736          // 512
#define OFF_B3  213248          // 32
#define OFF_ST  213280          // 2 buf x 4096 = 8192
#define SMEM_BYTES 221472

__device__ float g_x[BTOT * 4];
__device__ float g_ld[BTOT];
__device__ __half g_hh[(long)BTOT * 64];

__device__ __forceinline__ uint32_t smem_u32(const void* p) {
    return static_cast<uint32_t>(__cvta_generic_to_shared(p));
}
__device__ __forceinline__ void cp_async16(uint32_t dst, const void* src) {
    asm volatile("cp.async.cg.shared.global [%0], [%1], 16;"
                 :: "r"(dst), "l"(src) : "memory");
}
#define CP_COMMIT() asm volatile("cp.async.commit_group;" ::: "memory")
#define CP_WAIT0()  asm volatile("cp.async.wait_group 0;" ::: "memory")

__device__ __forceinline__ void ldsm_x4(uint32_t a, uint32_t& r0, uint32_t& r1,
                                        uint32_t& r2, uint32_t& r3) {
    asm volatile("ldmatrix.sync.aligned.m8n8.x4.shared.b16 {%0,%1,%2,%3},[%4];"
                 : "=r"(r0), "=r"(r1), "=r"(r2), "=r"(r3) : "r"(a));
}
__device__ __forceinline__ void ldsm_x4t(uint32_t a, uint32_t& r0, uint32_t& r1,
                                         uint32_t& r2, uint32_t& r3) {
    asm volatile("ldmatrix.sync.aligned.m8n8.x4.trans.shared.b16 {%0,%1,%2,%3},[%4];"
                 : "=r"(r0), "=r"(r1), "=r"(r2), "=r"(r3) : "r"(a));
}
__device__ __forceinline__ void ldsm_x2t(uint32_t a, uint32_t& r0, uint32_t& r1) {
    asm volatile("ldmatrix.sync.aligned.m8n8.x2.trans.shared.b16 {%0,%1},[%2];"
                 : "=r"(r0), "=r"(r1) : "r"(a));
}
// f16 x f16 -> f16 accum (C/D packed half2)
__device__ __forceinline__ void mma_h(uint32_t& c0, uint32_t& c1,
                                      const uint32_t* a, uint32_t b0, uint32_t b1) {
    asm volatile(
        "mma.sync.aligned.m16n8k16.row.col.f16.f16.f16.f16 "
        "{%0,%1},{%2,%3,%4,%5},{%6,%7},{%0,%1};"
        : "+r"(c0), "+r"(c1)
        : "r"(a[0]), "r"(a[1]), "r"(a[2]), "r"(a[3]), "r"(b0), "r"(b1));
}
// f16 x f16 -> f32 accum (GEMM3)
__device__ __forceinline__ void mma_hf32(float* c, const uint32_t* a,
                                         uint32_t b0, uint32_t b1) {
    asm volatile(
        "mma.sync.aligned.m16n8k16.row.col.f32.f16.f16.f32 "
        "{%0,%1,%2,%3},{%4,%5,%6,%7},{%8,%9},{%0,%1,%2,%3};"
        : "+f"(c[0]), "+f"(c[1]), "+f"(c[2]), "+f"(c[3])
        : "r"(a[0]), "r"(a[1]), "r"(a[2]), "r"(a[3]), "r"(b0), "r"(b1));
}
__device__ __forceinline__ uint32_t pack_h2(float lo, float hi) {
    __half2 v = __floats2half2_rn(lo, hi);
    return *reinterpret_cast<uint32_t*>(&v);
}
// packed half2 tanh-approx GELU
__device__ __forceinline__ uint32_t gelu2h(uint32_t xin) {
    __half2 x = *reinterpret_cast<__half2*>(&xin);
    const __half2 c1 = __floats2half2_rn(0.035677408136f, 0.035677408136f);
    const __half2 c0 = __floats2half2_rn(0.7978845608028654f, 0.7978845608028654f);
    const __half2 hf = __floats2half2_rn(0.5f, 0.5f);
    __half2 x2 = __hmul2(x, x);
    __half2 w  = __hfma2(x2, c1, c0);
    __half2 u  = __hmul2(x, w);
    uint32_t th;
    asm("tanh.approx.f16x2 %0, %1;"
        : "=r"(th) : "r"(*reinterpret_cast<uint32_t*>(&u)));
    __half2 hx = __hmul2(x, hf);
    __half2 r  = __hfma2(hx, *reinterpret_cast<__half2*>(&th), hx);
    return *reinterpret_cast<uint32_t*>(&r);
}

__device__ __forceinline__ void ldB4(const __half* p, uint32_t bf[4][4]) {
    #pragma unroll
    for (int q = 0; q < 4; q++)
        ldsm_x4t(smem_u32(p + q * 16), bf[q][0], bf[q][1], bf[q][2], bf[q][3]);
}
__device__ __forceinline__ void mma8h(uint32_t acc[8][2], const uint32_t* A,
                                      uint32_t bf[4][4]) {
    #pragma unroll
    for (int q = 0; q < 4; q++) {
        mma_h(acc[2 * q][0],     acc[2 * q][1],     A, bf[q][0], bf[q][1]);
        mma_h(acc[2 * q + 1][0], acc[2 * q + 1][1], A, bf[q][2], bf[q][3]);
    }
}

// ---- pre-pass: h fp32 -> f16 (run once per graph replay) ----
__global__ void __launch_bounds__(256)
cvt_h_kernel(const float* __restrict__ h) {
    long i = ((long)blockIdx.x * 256 + threadIdx.x) * 8;
    float4 a = *reinterpret_cast<const float4*>(h + i);
    float4 b = *reinterpret_cast<const float4*>(h + i + 4);
    uint4 o;
    o.x = pack_h2(a.x, a.y); o.y = pack_h2(a.z, a.w);
    o.z = pack_h2(b.x, b.y); o.w = pack_h2(b.z, b.w);
    *reinterpret_cast<uint4*>(g_hh + i) = o;
}

template <int LYR>
__global__ void __launch_bounds__(NTHREADS, 1)
nvp_layer(const float* __restrict__ theta, const float* __restrict__ h,
          const float* __restrict__ w1s, const float* __restrict__ b1s,
          const float* __restrict__ w2s, const float* __restrict__ b2s,
          const float* __restrict__ w3s, const float* __restrict__ b3s,
          const float* __restrict__ w1t, const float* __restrict__ b1t,
          const float* __restrict__ w2t, const float* __restrict__ b2t,
          const float* __restrict__ w3t, const float* __restrict__ b3t,
          float* __restrict__ out)
{
    constexpr bool FIRST = (LYR == 0);
    constexpr bool LAST  = (LYR == 3);
    // KEEP = ((0,1),(1,2),(2,3),(0,3)); TRANS = ((2,3),(0,3),(0,1),(1,2))
    constexpr int K0 = (LYR == 0) ? 0 : (LYR == 1) ? 1 : (LYR == 2) ? 2 : 0;
    constexpr int K1 = (LYR == 0) ? 1 : (LYR == 1) ? 2 : (LYR == 2) ? 3 : 3;
    constexpr int T0 = (LYR == 0) ? 2 : (LYR == 1) ? 0 : (LYR == 2) ? 0 : 1;
    constexpr int T1 = (LYR == 0) ? 3 : (LYR == 1) ? 3 : (LYR == 2) ? 1 : 2;

    extern __shared__ char smem[];
    const uint32_t smem_base = smem_u32(smem);
    __half* sW1 = reinterpret_cast<__half*>(smem + OFF_W1);
    __half* sW2 = reinterpret_cast<__half*>(smem + OFF_W2);
    __half* sW3 = reinterpret_cast<__half*>(smem + OFF_W3);
    uint32_t* sB1h = reinterpret_cast<uint32_t*>(smem + OFF_B1);
    uint32_t* sB2h = reinterpret_cast<uint32_t*>(smem + OFF_B2);
    float* sB3 = reinterpret_cast<float*>(smem + OFF_B3);

    const int tid = threadIdx.x;

    // ---- one-time weights -> smem ----
    for (int idx = tid; idx < 80 * W_LD; idx += NTHREADS) {
        int k = idx / W_LD, c = idx - k * W_LD;
        float v = 0.0f;
        if (c < 256) {
            const float* w1 = (c < 128) ? w1s : w1t;
            int cc = c & 127;
            if (k < 64)      v = w1[(k + 2) * 128 + cc];
            else if (k < 66) v = w1[(k - 64) * 128 + cc];
        }
        sW1[idx] = __float2half(v);
    }
    for (int idx = tid; idx < 128 * W_LD; idx += NTHREADS) {
        int k = idx / W_LD, c = idx - k * W_LD;
        float v = 0.0f;
        if (c < 256) v = (c < 128) ? w2s[k * 128 + c] : w2t[k * 128 + c - 128];
        sW2[idx] = __float2half(v);
    }
    for (int idx = tid; idx < 128 * W3_LD; idx += NTHREADS) {
        int k = idx >> 4, c = idx & 15;
        float v = 0.0f;
        if (c < 2) v = w3s[k * 2 + c];
        else if (c >= 8 && c < 10) v = w3t[k * 2 + c - 8];
        sW3[idx] = __float2half(v);
    }
    for (int i = tid; i < 128; i += NTHREADS) {
        int c = i * 2;
        float a1 = (c < 128) ? b1s[c] : b1t[c - 128];
        float b1v = (c + 1 < 128) ? b1s[c + 1] : b1t[c + 1 - 128];
        sB1h[i] = pack_h2(a1, b1v);
        float a2 = (c < 128) ? b2s[c] : b2t[c - 128];
        float b2v = (c + 1 < 128) ? b2s[c + 1] : b2t[c + 1 - 128];
        sB2h[i] = pack_h2(a2, b2v);
    }
    if (tid < 4) sB3[tid] = (tid < 2) ? b3s[tid] : b3t[tid - 2];
    // zero xp pad cols [66,88): 2 buffers x 2 tiles x 128 rows
    for (int idx = tid; idx < 4 * 128 * 22; idx += NTHREADS) {
        int rr = idx / 22, c = 66 + (idx - rr * 22);
        int bb = rr >> 8, tl = (rr >> 7) & 1, r = rr & 127;
        *reinterpret_cast<__half*>(
            smem + OFF_XP + bb * XP_P + tl * XP_T + (r * XP_LD + c) * 2) =
            __float2half(0.0f);
    }

    const int warp = tid >> 5;
    const int lane = tid & 31;
    const int net  = warp >> 3;       // 0 = s-net, 1 = t-net
    const int R0   = (warp & 7) * 16; // row block (same rows in both tiles)
    const int lg   = lane >> 3;
    const int lr   = lane & 7;
    const int l4   = lane & 3;

    // ---- prologue: prefetch pair0 into buf 0 ----
    const int p0 = blockIdx.x;
    {
        const __half* hsrc = g_hh + (long)p0 * 256 * 64;
        #pragma unroll
        for (int c = tid; c < 2048; c += NTHREADS) {
            int r = c >> 3, q = c & 7;
            uint32_t dst = smem_base + OFF_XP + (r >> 7) * XP_T
                         + (r & 127) * 176 + q * 16;
            cp_async16(dst, hsrc + r * 64 + q * 8);
        }
        if (tid < 256) {
            const float* xsrc = FIRST ? (theta + (long)(p0 * 256 + tid) * 4)
                                      : (g_x + (long)(p0 * 256 + tid) * 4);
            cp_async16(smem_base + OFF_XA + tid * 16, xsrc);
        }
        CP_COMMIT();
        CP_WAIT0();
        if (tid < 256) {
            float4 nx = *reinterpret_cast<float4*>(smem + OFF_XA + tid * 16);
            float c4[4] = {nx.x, nx.y, nx.z, nx.w};
            *reinterpret_cast<__half2*>(
                smem + OFF_XP + (tid >> 7) * XP_T + (tid & 127) * 176 + 128) =
                __floats2half2_rn(c4[K0], c4[K1]);
        }
    }
    __syncthreads();

    int buf = 0;
    for (int p = p0; p < NPAIRS; p += gridDim.x) {
        const int base = p * 256;
        const int np = p + gridDim.x;
        const bool has_next = (np < NPAIRS);

        // ---- prefetch next pair into buf^1 ----
        if (has_next) {
            const __half* hsrc = g_hh + (long)np * 256 * 64;
            uint32_t xpn = smem_base + OFF_XP + (buf ^ 1) * XP_P;
            #pragma unroll
            for (int c = tid; c < 2048; c += NTHREADS) {
                int r = c >> 3, q = c & 7;
                cp_async16(xpn + (r >> 7) * XP_T + (r & 127) * 176 + q * 16,
                           hsrc + r * 64 + q * 8);
            }
            if (tid < 256) {
                const float* xsrc = FIRST ? (theta + (long)(np * 256 + tid) * 4)
                                          : (g_x + (long)(np * 256 + tid) * 4);
                cp_async16(smem_base + OFF_XA + (buf ^ 1) * 4096 + tid * 16, xsrc);
            }
            CP_COMMIT();
        }

        float* sST = reinterpret_cast<float*>(smem + OFF_ST + buf * 4096);

        // ---- A frags (K=80) for both tiles ----
        const uint32_t apA = smem_base + OFF_XP + buf * XP_P
                           + (R0 + lr + (lg & 1) * 8) * 176 + (lg >> 1) * 16;
        const uint32_t apB = apA + XP_T;
        uint32_t axp[2][5][4];
        #pragma unroll
        for (int ks = 0; ks < 5; ks++) {
            ldsm_x4(apA + ks * 32, axp[0][ks][0], axp[0][ks][1],
                    axp[0][ks][2], axp[0][ks][3]);
            ldsm_x4(apB + ks * 32, axp[1][ks][0], axp[1][ks][1],
                    axp[1][ks][2], axp[1][ks][3]);
        }

        // ---- GEMM1 (2 chunks of N=64), dual-tile; hid1 in f16 regs ----
        uint32_t hfr[2][8][4];
        #pragma unroll
        for (int ch = 0; ch < 2; ch++) {
            uint32_t acc0[8][2], acc1[8][2];
            #pragma unroll
            for (int j = 0; j < 8; j++) {
                uint32_t bb = sB1h[net * 64 + ch * 32 + j * 4 + l4];
                acc0[j][0] = bb; acc0[j][1] = bb;
                acc1[j][0] = bb; acc1[j][1] = bb;
            }
            const __half* wb =
                &sW1[(lr + (lg & 1) * 8) * W_LD + net * 128 + ch * 64 + (lg >> 1) * 8];
            #pragma unroll
            for (int ks = 0; ks < 5; ks++) {
                uint32_t bf[4][4];
                ldB4(wb + ks * 16 * W_LD, bf);
                mma8h(acc0, axp[0][ks], bf);
                mma8h(acc1, axp[1][ks], bf);
            }
            #pragma unroll
            for (int kf = 0; kf < 4; kf++) {
                hfr[0][ch * 4 + kf][0] = gelu2h(acc0[2 * kf][0]);
                hfr[0][ch * 4 + kf][1] = gelu2h(acc0[2 * kf][1]);
                hfr[0][ch * 4 + kf][2] = gelu2h(acc0[2 * kf + 1][0]);
                hfr[0][ch * 4 + kf][3] = gelu2h(acc0[2 * kf + 1][1]);
                hfr[1][ch * 4 + kf][0] = gelu2h(acc1[2 * kf][0]);
                hfr[1][ch * 4 + kf][1] = gelu2h(acc1[2 * kf][1]);
                hfr[1][ch * 4 + kf][2] = gelu2h(acc1[2 * kf + 1][0]);
                hfr[1][ch * 4 + kf][3] = gelu2h(acc1[2 * kf + 1][1]);
            }
        }

        // ---- GEMM2 (2 chunks of N=64), dual-tile; GEMM3 fused ----
        float acc3[2][4] = {{0.f, 0.f, 0.f, 0.f}, {0.f, 0.f, 0.f, 0.f}};
        #pragma unroll
        for (int cc = 0; cc < 2; cc++) {
            uint32_t acc0[8][2], acc1[8][2];
            #pragma unroll
            for (int j = 0; j < 8; j++) {
                uint32_t bb = sB2h[net * 64 + cc * 32 + j * 4 + l4];
                acc0[j][0] = bb; acc0[j][1] = bb;
                acc1[j][0] = bb; acc1[j][1] = bb;
            }
            const __half* wb =
                &sW2[(lr + (lg & 1) * 8) * W_LD + net * 128 + cc * 64 + (lg >> 1) * 8];
            #pragma unroll
            for (int ks = 0; ks < 8; ks++) {
                uint32_t bf[4][4];
                ldB4(wb + ks * 16 * W_LD, bf);
                mma8h(acc0, hfr[0][ks], bf);
                mma8h(acc1, hfr[1][ks], bf);
            }
            uint32_t af0[4][4], af1[4][4];
            #pragma unroll
            for (int kf = 0; kf < 4; kf++) {
                af0[kf][0] = gelu2h(acc0[2 * kf][0]);
                af0[kf][1] = gelu2h(acc0[2 * kf][1]);
                af0[kf][2] = gelu2h(acc0[2 * kf + 1][0]);
                af0[kf][3] = gelu2h(acc0[2 * kf + 1][1]);
                af1[kf][0] = gelu2h(acc1[2 * kf][0]);
                af1[kf][1] = gelu2h(acc1[2 * kf][1]);
                af1[kf][2] = gelu2h(acc1[2 * kf + 1][0]);
                af1[kf][3] = gelu2h(acc1[2 * kf + 1][1]);
            }
            #pragma unroll
            for (int kf = 0; kf < 4; kf++) {
                int k0 = cc * 64 + kf * 16;
                uint32_t addr =
                    smem_u32(&sW3[(k0 + (lane & 15)) * W3_LD + net * 8]);
                uint32_t b0, b1;
                ldsm_x2t(addr, b0, b1);
                mma_hf32(acc3[0], af0[kf], b0, b1);
                mma_hf32(acc3[1], af1[kf], b0, b1);
            }
        }

        // ---- stage s/t into sST[buf] (per tile) ----
        if ((lane & 3) == 0) {
            int r1 = lane >> 2;
            #pragma unroll
            for (int mt = 0; mt < 2; mt++) {
                #pragma unroll
                for (int half = 0; half < 2; half++) {
                    int row = R0 + r1 + half * 8;
                    int idx = mt * 512 + (net * 128 + row) * 2;
                    sST[idx + 0] = acc3[mt][half * 2 + 0];
                    sST[idx + 1] = acc3[mt][half * 2 + 1];
                }
            }
        }

        // current-pair x into regs (sXA[buf] final since last iteration)
        float4 xv = make_float4(0.f, 0.f, 0.f, 0.f);
        if (tid < 256)
            xv = *reinterpret_cast<float4*>(smem + OFF_XA + buf * 4096 + tid * 16);

        // finish next-pair prefetch: wait + x-keep conversion into xp[buf^1]
        if (has_next) {
            CP_WAIT0();
            if (tid < 256) {
                float4 nx = *reinterpret_cast<float4*>(
                    smem + OFF_XA + (buf ^ 1) * 4096 + tid * 16);
                float c4[4] = {nx.x, nx.y, nx.z, nx.w};
                *reinterpret_cast<__half2*>(
                    smem + OFF_XP + (buf ^ 1) * XP_P + (tid >> 7) * XP_T
                    + (tid & 127) * 176 + 128) =
                    __floats2half2_rn(c4[K0], c4[K1]);
            }
        }
        __syncthreads();

        // ---- epilogue: one thread per row (256 rows) ----
        if (tid < 256) {
            int tl = tid >> 7, row = tid & 127;
            int b = base + tid;
            const float* st = sST + tl * 512;
            float s0 = st[row * 2 + 0] + sB3[0];
            float s1 = st[row * 2 + 1] + sB3[1];
            float t0 = st[(128 + row) * 2 + 0] + sB3[2];
            float t1 = st[(128 + row) * 2 + 1] + sB3[3];
            float xc[4] = {xv.x, xv.y, xv.z, xv.w};
            float nx0 = xc[T0] * __expf(s0) + t0;
            float nx1 = xc[T1] * __expf(s1) + t1;
            float ld = s0 + s1;
            if (!FIRST) ld += g_ld[b];
            xc[T0] = nx0;
            xc[T1] = nx1;
            if (!LAST) {
                reinterpret_cast<float4*>(g_x)[b] =
                    make_float4(xc[0], xc[1], xc[2], xc[3]);
                g_ld[b] = ld;
            } else {
                float ss = xc[0] * xc[0] + xc[1] * xc[1] +
                           xc[2] * xc[2] + xc[3] * xc[3];
                out[b] = -0.5f * ss - 3.6757541328186907f + ld;
            }
        }
        buf ^= 1;
    }
}

extern "C" void kernel_launch(void* const* d_in, const int* in_sizes, int n_in,
                              void* d_out, int out_size)
{
    const float* theta = (const float*)d_in[0];
    const float* h     = (const float*)d_in[1];
    const float* sW1   = (const float*)d_in[2];
    const float* sb1   = (const float*)d_in[3];
    const float* sW2   = (const float*)d_in[4];
    const float* sb2   = (const float*)d_in[5];
    const float* sW3   = (const float*)d_in[6];
    const float* sb3   = (const float*)d_in[7];
    const float* tW1   = (const float*)d_in[8];
    const float* tb1   = (const float*)d_in[9];
    const float* tW2   = (const float*)d_in[10];
    const float* tb2   = (const float*)d_in[11];
    const float* tW3   = (const float*)d_in[12];
    const float* tb3   = (const float*)d_in[13];
    float* out = (float*)d_out;

    int nsm = 148;
    cudaDeviceGetAttribute(&nsm, cudaDevAttrMultiProcessorCount, 0);

    cudaFuncSetAttribute(nvp_layer<0>, cudaFuncAttributeMaxDynamicSharedMemorySize, SMEM_BYTES);
    cudaFuncSetAttribute(nvp_layer<1>, cudaFuncAttributeMaxDynamicSharedMemorySize, SMEM_BYTES);
    cudaFuncSetAttribute(nvp_layer<2>, cudaFuncAttributeMaxDynamicSharedMemorySize, SMEM_BYTES);
    cudaFuncSetAttribute(nvp_layer<3>, cudaFuncAttributeMaxDynamicSharedMemorySize, SMEM_BYTES);

    // pre-pass: h -> f16 (BTOT*64 elems, 8 per thread, 256 threads/block)
    cvt_h_kernel<<<(BTOT * 64) / (8 * 256), 256>>>(h);

    dim3 grid(nsm), blk(NTHREADS);
    #define ARGS(L) theta, h,                                        \
        sW1 + (L) * 66 * 128, sb1 + (L) * 128,                       \
        sW2 + (L) * 128 * 128, sb2 + (L) * 128,                      \
        sW3 + (L) * 128 * 2, sb3 + (L) * 2,                          \
        tW1 + (L) * 66 * 128, tb1 + (L) * 128,                       \
        tW2 + (L) * 128 * 128, tb2 + (L) * 128,                      \
        tW3 + (L) * 128 * 2, tb3 + (L) * 2, out

    nvp_layer<0><<<grid, blk, SMEM_BYTES>>>(ARGS(0));
    nvp_layer<1><<<grid, blk, SMEM_BYTES>>>(ARGS(1));
    nvp_layer<2><<<grid, blk, SMEM_BYTES>>>(ARGS(2));
    nvp_layer<3><<<grid, blk, SMEM_BYTES>>>(ARGS(3));
    #undef ARGS
}